// round 16
// baseline (speedup 1.0000x reference)
#include <cuda_runtime.h>
#include <cuda_fp16.h>
#include <mma.h>
#include <cstdint>

using namespace nvcuda;

#define BB 4
#define NN 1024
#define JJ 2048
#define HH 16
#define DD 128
#define DIMM 2048
#define NQKV 6144
#define ROWS 4096

__device__ __half g_xn[(size_t)ROWS * DIMM];
__device__ __half g_qkv_h[(size_t)ROWS * NQKV];
__device__ __half g_qrot[(size_t)BB * HH * NN * DD];
__device__ __half g_krot[(size_t)BB * HH * JJ * DD];
__device__ __half g_vfull[(size_t)BB * HH * JJ * DD];
__device__ __half g_attnout[(size_t)ROWS * DIMM];
__device__ __half g_wqkv_h[(size_t)DIMM * NQKV];
__device__ __half g_wout_h[(size_t)DIMM * DIMM];
__device__ float  g_cos[JJ * DD];
__device__ float  g_sin[JJ * DD];

__device__ __forceinline__ void cpa16(void* smem, const void* gmem) {
    unsigned s = (unsigned)__cvta_generic_to_shared(smem);
    asm volatile("cp.async.cg.shared.global [%0], [%1], 16;\n" :: "r"(s), "l"(gmem));
}

__device__ __forceinline__ uint32_t smem_u32(const void* p) {
    uint32_t a;
    asm("{ .reg .u64 t; cvta.to.shared.u64 t, %1; cvt.u32.u64 %0, t; }" : "=r"(a) : "l"(p));
    return a;
}

__device__ __forceinline__ void ldsm4(uint32_t* r, uint32_t a) {
    asm volatile("ldmatrix.sync.aligned.m8n8.x4.shared.b16 {%0,%1,%2,%3}, [%4];"
                 : "=r"(r[0]), "=r"(r[1]), "=r"(r[2]), "=r"(r[3]) : "r"(a));
}
__device__ __forceinline__ void ldsm4t(uint32_t* r, uint32_t a) {
    asm volatile("ldmatrix.sync.aligned.m8n8.x4.trans.shared.b16 {%0,%1,%2,%3}, [%4];"
                 : "=r"(r[0]), "=r"(r[1]), "=r"(r[2]), "=r"(r[3]) : "r"(a));
}

__device__ __forceinline__ void mma16816(float* c, const uint32_t* a, uint32_t b0, uint32_t b1) {
    asm volatile(
        "mma.sync.aligned.m16n8k16.row.col.f32.f16.f16.f32 "
        "{%0,%1,%2,%3}, {%4,%5,%6,%7}, {%8,%9}, {%0,%1,%2,%3};"
        : "+f"(c[0]), "+f"(c[1]), "+f"(c[2]), "+f"(c[3])
        : "r"(a[0]), "r"(a[1]), "r"(a[2]), "r"(a[3]), "r"(b0), "r"(b1));
}

__device__ __forceinline__ uint32_t f2h2(float x, float y) {
    __half2 h = __floats2half2_rn(x, y);
    return *(uint32_t*)&h;
}

__device__ __forceinline__ float4 ld_half4(const __half* p) {
    uint2 u = *(const uint2*)p;
    __half2 a = *(__half2*)&u.x, b = *(__half2*)&u.y;
    float2 fa = __half22float2(a), fb = __half22float2(b);
    return make_float4(fa.x, fa.y, fb.x, fb.y);
}

// ---------------- merged prep: weight converts + rope table + rmsnorm ----------------
#define PREP_WQKV_BLKS 12288
#define PREP_WOUT_BLKS 4096
#define PREP_ROPE_BLKS 256
#define PREP_CONV_BLKS (PREP_WQKV_BLKS + PREP_WOUT_BLKS + PREP_ROPE_BLKS)
#define PREP_BLKS (PREP_CONV_BLKS + ROWS)

__global__ void __launch_bounds__(256) prep_kernel(const float* __restrict__ rot,
                                                   const float* __restrict__ wqkv,
                                                   const float* __restrict__ wout,
                                                   const float* __restrict__ x,
                                                   const float* __restrict__ w) {
    int bid = blockIdx.x;
    int tid = threadIdx.x;
    if (bid < PREP_WQKV_BLKS) {
        int idx = (bid * 256 + tid) * 4;
        float4 v = *(const float4*)(wqkv + idx);
        *(__half2*)(g_wqkv_h + idx)     = __floats2half2_rn(v.x, v.y);
        *(__half2*)(g_wqkv_h + idx + 2) = __floats2half2_rn(v.z, v.w);
    } else if (bid < PREP_WQKV_BLKS + PREP_WOUT_BLKS) {
        int idx = ((bid - PREP_WQKV_BLKS) * 256 + tid) * 4;
        float4 v = *(const float4*)(wout + idx);
        *(__half2*)(g_wout_h + idx)     = __floats2half2_rn(v.x, v.y);
        *(__half2*)(g_wout_h + idx + 2) = __floats2half2_rn(v.z, v.w);
    } else if (bid < PREP_CONV_BLKS) {
        int idx = ((bid - PREP_WQKV_BLKS - PREP_WOUT_BLKS) * 256 + tid) * 4;
        float4 p = *(const float4*)(rot + idx);
        *(float4*)&g_cos[idx] = make_float4(cosf(p.x), cosf(p.y), cosf(p.z), cosf(p.w));
        *(float4*)&g_sin[idx] = make_float4(sinf(p.x), sinf(p.y), sinf(p.z), sinf(p.w));
    } else {
        int row = bid - PREP_CONV_BLKS;
        const float4* xr = (const float4*)(x + (size_t)row * DIMM);
        float4 a = xr[tid];
        float4 b = xr[tid + 256];
        float ss = a.x * a.x + a.y * a.y + a.z * a.z + a.w * a.w
                 + b.x * b.x + b.y * b.y + b.z * b.z + b.w * b.w;
        #pragma unroll
        for (int o = 16; o; o >>= 1) ss += __shfl_xor_sync(0xffffffffu, ss, o);
        __shared__ float red[8];
        if ((tid & 31) == 0) red[tid >> 5] = ss;
        __syncthreads();
        float tot = red[0] + red[1] + red[2] + red[3] + red[4] + red[5] + red[6] + red[7];
        float inv = rsqrtf(tot * (1.0f / (float)DIMM) + 1.1920929e-7f);

        const float4* wr = (const float4*)w;
        float4 wa = wr[tid];
        float4 wb = wr[tid + 256];
        uint2 o0, o1;
        o0.x = f2h2(a.x * inv * wa.x, a.y * inv * wa.y);
        o0.y = f2h2(a.z * inv * wa.z, a.w * inv * wa.w);
        o1.x = f2h2(b.x * inv * wb.x, b.y * inv * wb.y);
        o1.y = f2h2(b.z * inv * wb.z, b.w * inv * wb.w);
        *(uint2*)&g_xn[(size_t)row * DIMM + tid * 4]        = o0;
        *(uint2*)&g_xn[(size_t)row * DIMM + 1024 + tid * 4] = o1;
    }
}

// ---------------- fp16 GEMM v1: block 128x256, warp 64x64, KSTEP 64, 4-stage (out-proj, fp32 out) ----------------
#define GS 4
#define A_LD 72
#define B_LD 264
#define ASZ (128 * A_LD)
#define BSZ (64 * B_LD)
#define G_SMEM_BYTES (GS * (ASZ + BSZ) * 2)

__global__ void __launch_bounds__(256, 1) gemm_hp(const __half* __restrict__ A,
                                                  const __half* __restrict__ B,
                                                  float* __restrict__ C,
                                                  int M, int N, int K) {
    extern __shared__ __half hsm[];
    __half* As = hsm;
    __half* Bs = hsm + GS * ASZ;

    int tid = threadIdx.x;
    int n0 = blockIdx.x * 256;
    int m0 = blockIdx.y * 128;
    int w = tid >> 5;
    int wm = w >> 2;
    int wn = w & 3;

    wmma::fragment<wmma::accumulator, 16, 16, 16, float> acc[4][4];
    #pragma unroll
    for (int i = 0; i < 4; i++)
        #pragma unroll
        for (int j = 0; j < 4; j++) wmma::fill_fragment(acc[i][j], 0.0f);

    #define LOAD_STAGE(st, kk)                                                          \
        {                                                                               \
            __half* as_ = As + (st) * ASZ;                                              \
            __half* bs_ = Bs + (st) * BSZ;                                              \
            _Pragma("unroll")                                                           \
            for (int i = 0; i < 4; i++) {                                               \
                int c = tid + 256 * i;                                                  \
                int r = c >> 3, c8 = (c & 7) * 8;                                       \
                cpa16(&as_[r * A_LD + c8], &A[(size_t)(m0 + r) * K + (kk) + c8]);       \
            }                                                                           \
            _Pragma("unroll")                                                           \
            for (int i = 0; i < 8; i++) {                                               \
                int c = tid + 256 * i;                                                  \
                int r = c >> 5, c8 = (c & 31) * 8;                                      \
                cpa16(&bs_[r * B_LD + c8], &B[(size_t)((kk) + r) * N + n0 + c8]);       \
            }                                                                           \
            asm volatile("cp.async.commit_group;\n");                                   \
        }

    LOAD_STAGE(0, 0);
    LOAD_STAGE(1, 64);
    LOAD_STAGE(2, 128);

    int nk = K >> 6;
    for (int kt = 0; kt < nk; kt++) {
        int rem = nk - 1 - kt;
        if (rem >= 2)      asm volatile("cp.async.wait_group 2;\n");
        else if (rem == 1) asm volatile("cp.async.wait_group 1;\n");
        else               asm volatile("cp.async.wait_group 0;\n");
        __syncthreads();

        if (kt + 3 < nk) {
            LOAD_STAGE((kt + 3) & 3, (kt + 3) << 6);
        }

        const __half* as = As + (kt & 3) * ASZ;
        const __half* bs = Bs + (kt & 3) * BSZ;

        #pragma unroll
        for (int kf = 0; kf < 4; kf++) {
            wmma::fragment<wmma::matrix_a, 16, 16, 16, __half, wmma::row_major> af[4];
            wmma::fragment<wmma::matrix_b, 16, 16, 16, __half, wmma::row_major> bf[4];
            #pragma unroll
            for (int i = 0; i < 4; i++)
                wmma::load_matrix_sync(af[i], &as[(wm * 64 + i * 16) * A_LD + kf * 16], A_LD);
            #pragma unroll
            for (int j = 0; j < 4; j++)
                wmma::load_matrix_sync(bf[j], &bs[(kf * 16) * B_LD + wn * 64 + j * 16], B_LD);
            #pragma unroll
            for (int i = 0; i < 4; i++)
                #pragma unroll
                for (int j = 0; j < 4; j++)
                    wmma::mma_sync(acc[i][j], af[i], bf[j], acc[i][j]);
        }
    }

    #pragma unroll
    for (int i = 0; i < 4; i++)
        #pragma unroll
        for (int j = 0; j < 4; j++)
            wmma::store_matrix_sync(&C[(size_t)(m0 + wm * 64 + i * 16) * N + n0 + wn * 64 + j * 16],
                                    acc[i][j], N, wmma::mem_row_major);
    #undef LOAD_STAGE
}

// ---------------- fp16 GEMM v2: block 128x192, warp 64x48, KSTEP 64, 4-stage (QKV; half output) ----------------
#define A_LD2 72
#define B_LD2 200
#define ASZ2 (128 * A_LD2)
#define BSZ2 (64 * B_LD2)
#define G2_SMEM_BYTES (GS * (ASZ2 + BSZ2) * 2)

__global__ void __launch_bounds__(256, 1) gemm_hp192(const __half* __restrict__ A,
                                                     const __half* __restrict__ B,
                                                     __half* __restrict__ C,
                                                     int M, int N, int K) {
    extern __shared__ __half hsm[];
    __half* As = hsm;
    __half* Bs = hsm + GS * ASZ2;

    int tid = threadIdx.x;
    int lane = tid & 31;
    int n0 = blockIdx.x * 192;
    int m0 = blockIdx.y * 128;
    int w = tid >> 5;
    int wm = w >> 2;
    int wn = w & 3;

    wmma::fragment<wmma::accumulator, 16, 16, 16, float> acc[4][3];
    #pragma unroll
    for (int i = 0; i < 4; i++)
        #pragma unroll
        for (int j = 0; j < 3; j++) wmma::fill_fragment(acc[i][j], 0.0f);

    #define LOAD_STAGE2(st, kk)                                                         \
        {                                                                               \
            __half* as_ = As + (st) * ASZ2;                                             \
            __half* bs_ = Bs + (st) * BSZ2;                                             \
            _Pragma("unroll")                                                           \
            for (int i = 0; i < 4; i++) {                                               \
                int c = tid + 256 * i;                                                  \
                int r = c >> 3, c8 = (c & 7) * 8;                                       \
                cpa16(&as_[r * A_LD2 + c8], &A[(size_t)(m0 + r) * K + (kk) + c8]);      \
            }                                                                           \
            _Pragma("unroll")                                                           \
            for (int i = 0; i < 6; i++) {                                               \
                int c = tid + 256 * i;                                                  \
                int r = c / 24, cc = (c % 24) * 8;                                      \
                cpa16(&bs_[r * B_LD2 + cc], &B[(size_t)((kk) + r) * N + n0 + cc]);      \
            }                                                                           \
            asm volatile("cp.async.commit_group;\n");                                   \
        }

    LOAD_STAGE2(0, 0);
    LOAD_STAGE2(1, 64);
    LOAD_STAGE2(2, 128);

    int nk = K >> 6;
    for (int kt = 0; kt < nk; kt++) {
        int rem = nk - 1 - kt;
        if (rem >= 2)      asm volatile("cp.async.wait_group 2;\n");
        else if (rem == 1) asm volatile("cp.async.wait_group 1;\n");
        else               asm volatile("cp.async.wait_group 0;\n");
        __syncthreads();

        if (kt + 3 < nk) {
            LOAD_STAGE2((kt + 3) & 3, (kt + 3) << 6);
        }

        const __half* as = As + (kt & 3) * ASZ2;
        const __half* bs = Bs + (kt & 3) * BSZ2;

        #pragma unroll
        for (int kf = 0; kf < 4; kf++) {
            wmma::fragment<wmma::matrix_a, 16, 16, 16, __half, wmma::row_major> af[4];
            wmma::fragment<wmma::matrix_b, 16, 16, 16, __half, wmma::row_major> bf[3];
            #pragma unroll
            for (int i = 0; i < 4; i++)
                wmma::load_matrix_sync(af[i], &as[(wm * 64 + i * 16) * A_LD2 + kf * 16], A_LD2);
            #pragma unroll
            for (int j = 0; j < 3; j++)
                wmma::load_matrix_sync(bf[j], &bs[(kf * 16) * B_LD2 + wn * 48 + j * 16], B_LD2);
            #pragma unroll
            for (int i = 0; i < 4; i++)
                #pragma unroll
                for (int j = 0; j < 3; j++)
                    wmma::mma_sync(acc[i][j], af[i], bf[j], acc[i][j]);
        }
    }

    __syncthreads();
    float* stage = (float*)hsm + w * (16 * 52);
    #pragma unroll
    for (int i = 0; i < 4; i++) {
        #pragma unroll
        for (int j = 0; j < 3; j++)
            wmma::store_matrix_sync(stage + j * 16, acc[i][j], 52, wmma::mem_row_major);
        __syncwarp();
        int rbase = m0 + wm * 64 + i * 16;
        #pragma unroll
        for (int e = 0; e < 12; e++) {
            int idx = lane + e * 32;
            int r = idx / 24, c2 = (idx % 24) * 2;
            float x0 = stage[r * 52 + c2];
            float x1 = stage[r * 52 + c2 + 1];
            *(uint32_t*)&C[(size_t)(rbase + r) * N + n0 + wn * 48 + c2] = f2h2(x0, x1);
        }
        __syncwarp();
    }
    #undef LOAD_STAGE2
}

// ---------------- scatter + rotary: q pre-scaled by 1/sqrt(d) ----------------
#define QSCALE 0.08838834764831845f

__global__ void __launch_bounds__(256) scatter_rotary_kernel(const float* __restrict__ cache,
                                                             float* __restrict__ kv_out) {
    int idx = blockIdx.x * 256 + threadIdx.x;
    int d4 = (idx & 15) * 4;
    int j  = (idx >> 4) & 2047;
    int h  = (idx >> 15) & 15;
    int b  = idx >> 19;

    float4 cl = *(const float4*)&g_cos[j * DD + d4];
    float4 ch = *(const float4*)&g_cos[j * DD + d4 + 64];
    float4 sl = *(const float4*)&g_sin[j * DD + d4];
    float4 sh = *(const float4*)&g_sin[j * DD + d4 + 64];

    float4 kl, kh, vl, vh;
    if (j < 1024) {
        const float* ckb = cache + (((size_t)(b * 2 + 0) * HH + h) * 1024 + j) * DD;
        const float* cvb = cache + (((size_t)(b * 2 + 1) * HH + h) * 1024 + j) * DD;
        kl = *(const float4*)(ckb + d4);
        kh = *(const float4*)(ckb + d4 + 64);
        vl = *(const float4*)(cvb + d4);
        vh = *(const float4*)(cvb + d4 + 64);
    } else {
        int rrow = b * NN + (j - 1024);
        const __half* qr = g_qkv_h + (size_t)rrow * NQKV;
        kl = ld_half4(qr + 2048 + h * DD + d4);
        kh = ld_half4(qr + 2048 + h * DD + d4 + 64);
        vl = ld_half4(qr + 4096 + h * DD + d4);
        vh = ld_half4(qr + 4096 + h * DD + d4 + 64);
        float4 ql = ld_half4(qr + h * DD + d4);
        float4 qh = ld_half4(qr + h * DD + d4 + 64);
        size_t qidx = (((size_t)(b * HH + h) * NN + (j - 1024)) * DD) + d4;
        uint2 qlo, qhi;
        qlo.x = f2h2((ql.x * cl.x - qh.x * sl.x) * QSCALE, (ql.y * cl.y - qh.y * sl.y) * QSCALE);
        qlo.y = f2h2((ql.z * cl.z - qh.z * sl.z) * QSCALE, (ql.w * cl.w - qh.w * sl.w) * QSCALE);
        qhi.x = f2h2((qh.x * ch.x + ql.x * sh.x) * QSCALE, (qh.y * ch.y + ql.y * sh.y) * QSCALE);
        qhi.y = f2h2((qh.z * ch.z + ql.z * sh.z) * QSCALE, (qh.w * ch.w + ql.w * sh.w) * QSCALE);
        *(uint2*)&g_qrot[qidx]      = qlo;
        *(uint2*)&g_qrot[qidx + 64] = qhi;
    }

    size_t kvidx = ((size_t)(b * HH + h) * JJ + j) * DD + d4;
    uint2 klo, khi, vlo, vhi;
    klo.x = f2h2(kl.x * cl.x - kh.x * sl.x, kl.y * cl.y - kh.y * sl.y);
    klo.y = f2h2(kl.z * cl.z - kh.z * sl.z, kl.w * cl.w - kh.w * sl.w);
    khi.x = f2h2(kh.x * ch.x + kl.x * sh.x, kh.y * ch.y + kl.y * sh.y);
    khi.y = f2h2(kh.z * ch.z + kl.z * sh.z, kh.w * ch.w + kl.w * sh.w);
    vlo.x = f2h2(vl.x, vl.y);  vlo.y = f2h2(vl.z, vl.w);
    vhi.x = f2h2(vh.x, vh.y);  vhi.y = f2h2(vh.z, vh.w);
    *(uint2*)&g_krot[kvidx]       = klo;
    *(uint2*)&g_krot[kvidx + 64]  = khi;
    *(uint2*)&g_vfull[kvidx]      = vlo;
    *(uint2*)&g_vfull[kvidx + 64] = vhi;

    float* ko = &kv_out[(((size_t)(b * 2 + 0) * HH + h) * JJ + j) * DD + d4];
    float* vo = &kv_out[(((size_t)(b * 2 + 1) * HH + h) * JJ + j) * DD + d4];
    *(float4*)(ko)      = kl;
    *(float4*)(ko + 64) = kh;
    *(float4*)(vo)      = vl;
    *(float4*)(vo + 64) = vh;
}

// ---------------- flash attention: 64-key tiles, ldmatrix Q reload, low regs ----------------
#define KLD 136
#define QTILE_H (128 * KLD)
#define KVTILE_H (64 * KLD)
#define AT_SMEM_BYTES ((QTILE_H + 4 * KVTILE_H) * 2 + 2 * 64 * 4)

__global__ void __launch_bounds__(256, 1) attn_kernel(const int* __restrict__ mask) {
    extern __shared__ char asmem[];
    __half* Qs = (__half*)asmem;
    __half* Kb[2] = { Qs + QTILE_H,               Qs + QTILE_H + 2 * KVTILE_H };
    __half* Vb[2] = { Qs + QTILE_H + KVTILE_H,    Qs + QTILE_H + 3 * KVTILE_H };
    int* Ms = (int*)(Qs + QTILE_H + 4 * KVTILE_H);

    int tid = threadIdx.x;
    int w = tid >> 5;
    int lane = tid & 31;
    int g = lane >> 2;
    int t2 = (lane & 3) * 2;

    int bid = blockIdx.x;
    int b  = bid & 3;
    int h  = (bid >> 2) & 15;
    int qb = 7 - (bid >> 6);
    int m0 = qb * 128;

    const __half* qp = g_qrot + ((size_t)(b * HH + h) * NN + m0) * DD;
    const __half* kp = g_krot + (size_t)(b * HH + h) * JJ * DD;
    const __half* vp = g_vfull + (size_t)(b * HH + h) * JJ * DD;
    const int* mrow = mask + (size_t)b * JJ;

    int nt = 2 * qb + 18;    // 64-key tiles covering causal span

    #pragma unroll
    for (int i = tid; i < 128 * 16; i += 256) {
        int r = i >> 4, c8 = (i & 15) * 8;
        *(float4*)&Qs[r * KLD + c8] = *(const float4*)&qp[(size_t)r * DD + c8];
    }
    if (tid < 64) Ms[tid] = mrow[tid];
    #pragma unroll
    for (int i = tid; i < 64 * 16; i += 256) {
        int r = i >> 4, c8 = (i & 15) * 8;
        cpa16(&Kb[0][r * KLD + c8], &kp[(size_t)r * DD + c8]);
    }
    asm volatile("cp.async.commit_group;\n");
    #pragma unroll
    for (int i = tid; i < 64 * 16; i += 256) {
        int r = i >> 4, c8 = (i & 15) * 8;
        cpa16(&Vb[0][r * KLD + c8], &vp[(size_t)r * DD + c8]);
    }
    asm volatile("cp.async.commit_group;\n");
    __syncthreads();

    float oc[16][4];
    #pragma unroll
    for (int n = 0; n < 16; n++)
        #pragma unroll
        for (int i = 0; i < 4; i++) oc[n][i] = 0.0f;

    float m0r = -1e30f, m1r = -1e30f;
    float l0 = 0.0f, l1 = 0.0f;
    int row0 = m0 + w * 16 + g;
    int rowlim0 = row0 + 1024;
    int rowlim1 = rowlim0 + 8;

    // ldmatrix per-lane offsets (bytes)
    uint32_t qoff = ((w * 16 + (lane & 7) + ((lane >> 3) & 1) * 8) * KLD + (lane >> 4) * 8) * 2;
    uint32_t koff = ((lane & 7) * KLD + (lane >> 3) * 8) * 2;
    uint32_t voff = ((((lane >> 3) & 1) * 8 + (lane & 7)) * KLD + (lane >> 4) * 8) * 2;
    uint32_t qbase = smem_u32(Qs) + qoff;

    for (int kt = 0; kt < nt; kt++) {
        asm volatile("cp.async.wait_group 0;\n");
        __syncthreads();

        if (tid < 64 && kt + 1 < nt) Ms[((kt + 1) & 1) * 64 + tid] = mrow[(kt + 1) * 64 + tid];

        if (kt + 1 < nt) {
            int bn = (kt + 1) & 1;
            #pragma unroll
            for (int i = tid; i < 64 * 16; i += 256) {
                int r = i >> 4, c8 = (i & 15) * 8;
                cpa16(&Kb[bn][r * KLD + c8], &kp[(size_t)((kt + 1) * 64 + r) * DD + c8]);
            }
            asm volatile("cp.async.commit_group;\n");
            #pragma unroll
            for (int i = tid; i < 64 * 16; i += 256) {
                int r = i >> 4, c8 = (i & 15) * 8;
                cpa16(&Vb[bn][r * KLD + c8], &vp[(size_t)((kt + 1) * 64 + r) * DD + c8]);
            }
            asm volatile("cp.async.commit_group;\n");
        }

        const __half* Kt = Kb[kt & 1];
        const __half* Vt = Vb[kt & 1];
        const int* Mt = Ms + (kt & 1) * 64;

        // S = Q K^T (Q pre-scaled); Q fragments reloaded from smem per k-slab
        float sc[8][4];
        #pragma unroll
        for (int n = 0; n < 8; n++)
            #pragma unroll
            for (int i = 0; i < 4; i++) sc[n][i] = 0.0f;

        uint32_t ktu = smem_u32(Kt) + koff;
        #pragma unroll
        for (int ksp = 0; ksp < 4; ksp++) {
            uint32_t qa0[4], qa1[4];
            ldsm4(qa0, qbase + (uint32_t)(ksp * 32) * 2);
            ldsm4(qa1, qbase + (uint32_t)(ksp * 32 + 16) * 2);
            #pragma unroll
            for (int nb = 0; nb < 8; nb++) {
                uint32_t br[4];
                ldsm4(br, ktu + (uint32_t)(nb * 8 * KLD + ksp * 32) * 2);
                mma16816(sc[nb], qa0, br[0], br[1]);
                mma16816(sc[nb], qa1, br[2], br[3]);
            }
        }

        // mask + row max
        bool lastt = (kt >= nt - 2);
        float mx0 = -1e30f, mx1 = -1e30f;
        #pragma unroll
        for (int nb = 0; nb < 8; nb++) {
            int col = kt * 64 + nb * 8 + t2;
            int2 mv = *(const int2*)&Mt[nb * 8 + t2];
            float v0 = sc[nb][0];
            float v1 = sc[nb][1];
            float v2 = sc[nb][2];
            float v3 = sc[nb][3];
            if (mv.x == 0) { v0 = -1e30f; v2 = -1e30f; }
            if (mv.y == 0) { v1 = -1e30f; v3 = -1e30f; }
            if (lastt) {
                if (col     > rowlim0) v0 = -1e30f;
                if (col + 1 > rowlim0) v1 = -1e30f;
                if (col     > rowlim1) v2 = -1e30f;
                if (col + 1 > rowlim1) v3 = -1e30f;
            }
            sc[nb][0] = v0; sc[nb][1] = v1; sc[nb][2] = v2; sc[nb][3] = v3;
            mx0 = fmaxf(mx0, fmaxf(v0, v1));
            mx1 = fmaxf(mx1, fmaxf(v2, v3));
        }
        mx0 = fmaxf(mx0, __shfl_xor_sync(0xffffffffu, mx0, 1));
        mx0 = fmaxf(mx0, __shfl_xor_sync(0xffffffffu, mx0, 2));
        mx1 = fmaxf(mx1, __shfl_xor_sync(0xffffffffu, mx1, 1));
        mx1 = fmaxf(mx1, __shfl_xor_sync(0xffffffffu, mx1, 2));

        float mn0 = fmaxf(m0r, mx0), mn1 = fmaxf(m1r, mx1);
        float al0 = __expf(m0r - mn0), al1 = __expf(m1r - mn1);
        m0r = mn0; m1r = mn1;

        // exp + pack to half (sc dies here)
        uint32_t ph0[8], ph1[8];
        float s0 = 0.0f, s1 = 0.0f;
        #pragma unroll
        for (int nb = 0; nb < 8; nb++) {
            float p0 = __expf(sc[nb][0] - mn0);
            float p1 = __expf(sc[nb][1] - mn0);
            float p2 = __expf(sc[nb][2] - mn1);
            float p3 = __expf(sc[nb][3] - mn1);
            s0 += p0 + p1; s1 += p2 + p3;
            ph0[nb] = f2h2(p0, p1);
            ph1[nb] = f2h2(p2, p3);
        }
        l0 = l0 * al0 + s0;
        l1 = l1 * al1 + s1;
        #pragma unroll
        for (int n = 0; n < 16; n++) {
            oc[n][0] *= al0; oc[n][1] *= al0;
            oc[n][2] *= al1; oc[n][3] *= al1;
        }

        // PV: 4 key-chunks of 16
        uint32_t vtu = smem_u32(Vt) + voff;
        #pragma unroll
        for (int kk = 0; kk < 4; kk++) {
            uint32_t pa[4];
            pa[0] = ph0[2 * kk];
            pa[1] = ph1[2 * kk];
            pa[2] = ph0[2 * kk + 1];
            pa[3] = ph1[2 * kk + 1];
            #pragma unroll
            for (int ndp = 0; ndp < 8; ndp++) {
                uint32_t br[4];
                ldsm4t(br, vtu + (uint32_t)(kk * 16 * KLD + ndp * 16) * 2);
                mma16816(oc[2 * ndp],     pa, br[0], br[1]);
                mma16816(oc[2 * ndp + 1], pa, br[2], br[3]);
            }
        }
    }

    l0 += __shfl_xor_sync(0xffffffffu, l0, 1);
    l0 += __shfl_xor_sync(0xffffffffu, l0, 2);
    l1 += __shfl_xor_sync(0xffffffffu, l1, 1);
    l1 += __shfl_xor_sync(0xffffffffu, l1, 2);
    float inv0 = 1.0f / l0, inv1 = 1.0f / l1;

    __half* out0 = g_attnout + (size_t)(b * NN + row0) * DIMM + h * DD;
    __half* out1 = out0 + (size_t)8 * DIMM;
    #pragma unroll
    for (int nd = 0; nd < 16; nd++) {
        *(uint32_t*)&out0[nd * 8 + t2] = f2h2(oc[nd][0] * inv0, oc[nd][1] * inv0);
        *(uint32_t*)&out1[nd * 8 + t2] = f2h2(oc[nd][2] * inv1, oc[nd][3] * inv1);
    }
}

// ---------------- launch ----------------
extern "C" void kernel_launch(void* const* d_in, const int* in_sizes, int n_in,
                              void* d_out, int out_size) {
    const float* x       = (const float*)d_in[0];
    const float* cache   = (const float*)d_in[1];
    const float* rotary  = (const float*)d_in[2];
    const int*   mask    = (const int*)d_in[3];
    const float* norm_w  = (const float*)d_in[4];
    const float* w_qkv   = (const float*)d_in[5];
    const float* w_out   = (const float*)d_in[6];

    float* out    = (float*)d_out;
    float* kv_out = out + (size_t)ROWS * DIMM;

    __half *xn_ptr, *wqkv_ptr, *wout_ptr, *ao_ptr, *qkvh_ptr;
    cudaGetSymbolAddress((void**)&xn_ptr, g_xn);
    cudaGetSymbolAddress((void**)&qkvh_ptr, g_qkv_h);
    cudaGetSymbolAddress((void**)&ao_ptr, g_attnout);
    cudaGetSymbolAddress((void**)&wqkv_ptr, g_wqkv_h);
    cudaGetSymbolAddress((void**)&wout_ptr, g_wout_h);

    cudaFuncSetAttribute(attn_kernel, cudaFuncAttributeMaxDynamicSharedMemorySize, AT_SMEM_BYTES);
    cudaFuncSetAttribute(gemm_hp, cudaFuncAttributeMaxDynamicSharedMemorySize, G_SMEM_BYTES);
    cudaFuncSetAttribute(gemm_hp192, cudaFuncAttributeMaxDynamicSharedMemorySize, G2_SMEM_BYTES);

    prep_kernel<<<PREP_BLKS, 256>>>(rotary, w_qkv, w_out, x, norm_w);

    gemm_hp192<<<dim3(NQKV / 192, ROWS / 128), 256, G2_SMEM_BYTES>>>(xn_ptr, wqkv_ptr, qkvh_ptr,
                                                                     ROWS, NQKV, DIMM);

    scatter_rotary_kernel<<<(BB * HH * JJ * 16) / 256, 256>>>(cache, kv_out);

    attn_kernel<<<BB * HH * (NN / 128), 256, AT_SMEM_BYTES>>>(mask);

    gemm_hp<<<dim3(DIMM / 256, ROWS / 128), 256, G_SMEM_BYTES>>>(ao_ptr, wout_ptr, out,
                                                                 ROWS, DIMM, DIMM);
}

// round 17
// speedup vs baseline: 1.0412x; 1.0412x over previous
#include <cuda_runtime.h>
#include <cuda_fp16.h>
#include <mma.h>
#include <cstdint>

using namespace nvcuda;

#define BB 4
#define NN 1024
#define JJ 2048
#define HH 16
#define DD 128
#define DIMM 2048
#define NQKV 6144
#define ROWS 4096

__device__ __half g_xn[(size_t)ROWS * DIMM];
__device__ __half g_qkv_h[(size_t)ROWS * NQKV];
__device__ __half g_qrot[(size_t)BB * HH * NN * DD];
__device__ __half g_krot[(size_t)BB * HH * JJ * DD];
__device__ __half g_vfull[(size_t)BB * HH * JJ * DD];
__device__ __half g_attnout[(size_t)ROWS * DIMM];
__device__ __half g_wqkv_h[(size_t)DIMM * NQKV];
__device__ __half g_wout_h[(size_t)DIMM * DIMM];
__device__ float  g_cos[JJ * DD];
__device__ float  g_sin[JJ * DD];

__device__ __forceinline__ void cpa16(void* smem, const void* gmem) {
    unsigned s = (unsigned)__cvta_generic_to_shared(smem);
    asm volatile("cp.async.cg.shared.global [%0], [%1], 16;\n" :: "r"(s), "l"(gmem));
}

__device__ __forceinline__ uint32_t smem_u32(const void* p) {
    uint32_t a;
    asm("{ .reg .u64 t; cvta.to.shared.u64 t, %1; cvt.u32.u64 %0, t; }" : "=r"(a) : "l"(p));
    return a;
}

__device__ __forceinline__ void ldsm4(uint32_t* r, uint32_t a) {
    asm volatile("ldmatrix.sync.aligned.m8n8.x4.shared.b16 {%0,%1,%2,%3}, [%4];"
                 : "=r"(r[0]), "=r"(r[1]), "=r"(r[2]), "=r"(r[3]) : "r"(a));
}
__device__ __forceinline__ void ldsm4t(uint32_t* r, uint32_t a) {
    asm volatile("ldmatrix.sync.aligned.m8n8.x4.trans.shared.b16 {%0,%1,%2,%3}, [%4];"
                 : "=r"(r[0]), "=r"(r[1]), "=r"(r[2]), "=r"(r[3]) : "r"(a));
}

__device__ __forceinline__ void mma16816(float* c, const uint32_t* a, uint32_t b0, uint32_t b1) {
    asm volatile(
        "mma.sync.aligned.m16n8k16.row.col.f32.f16.f16.f32 "
        "{%0,%1,%2,%3}, {%4,%5,%6,%7}, {%8,%9}, {%0,%1,%2,%3};"
        : "+f"(c[0]), "+f"(c[1]), "+f"(c[2]), "+f"(c[3])
        : "r"(a[0]), "r"(a[1]), "r"(a[2]), "r"(a[3]), "r"(b0), "r"(b1));
}

__device__ __forceinline__ uint32_t f2h2(float x, float y) {
    __half2 h = __floats2half2_rn(x, y);
    return *(uint32_t*)&h;
}

__device__ __forceinline__ float4 ld_half4(const __half* p) {
    uint2 u = *(const uint2*)p;
    __half2 a = *(__half2*)&u.x, b = *(__half2*)&u.y;
    float2 fa = __half22float2(a), fb = __half22float2(b);
    return make_float4(fa.x, fa.y, fb.x, fb.y);
}

// ---------------- merged prep: weight converts + rope table + rmsnorm ----------------
#define PREP_WQKV_BLKS 12288
#define PREP_WOUT_BLKS 4096
#define PREP_ROPE_BLKS 256
#define PREP_CONV_BLKS (PREP_WQKV_BLKS + PREP_WOUT_BLKS + PREP_ROPE_BLKS)
#define PREP_BLKS (PREP_CONV_BLKS + ROWS)

__global__ void __launch_bounds__(256) prep_kernel(const float* __restrict__ rot,
                                                   const float* __restrict__ wqkv,
                                                   const float* __restrict__ wout,
                                                   const float* __restrict__ x,
                                                   const float* __restrict__ w) {
    int bid = blockIdx.x;
    int tid = threadIdx.x;
    if (bid < PREP_WQKV_BLKS) {
        int idx = (bid * 256 + tid) * 4;
        float4 v = *(const float4*)(wqkv + idx);
        *(__half2*)(g_wqkv_h + idx)     = __floats2half2_rn(v.x, v.y);
        *(__half2*)(g_wqkv_h + idx + 2) = __floats2half2_rn(v.z, v.w);
    } else if (bid < PREP_WQKV_BLKS + PREP_WOUT_BLKS) {
        int idx = ((bid - PREP_WQKV_BLKS) * 256 + tid) * 4;
        float4 v = *(const float4*)(wout + idx);
        *(__half2*)(g_wout_h + idx)     = __floats2half2_rn(v.x, v.y);
        *(__half2*)(g_wout_h + idx + 2) = __floats2half2_rn(v.z, v.w);
    } else if (bid < PREP_CONV_BLKS) {
        int idx = ((bid - PREP_WQKV_BLKS - PREP_WOUT_BLKS) * 256 + tid) * 4;
        float4 p = *(const float4*)(rot + idx);
        *(float4*)&g_cos[idx] = make_float4(cosf(p.x), cosf(p.y), cosf(p.z), cosf(p.w));
        *(float4*)&g_sin[idx] = make_float4(sinf(p.x), sinf(p.y), sinf(p.z), sinf(p.w));
    } else {
        int row = bid - PREP_CONV_BLKS;
        const float4* xr = (const float4*)(x + (size_t)row * DIMM);
        float4 a = xr[tid];
        float4 b = xr[tid + 256];
        float ss = a.x * a.x + a.y * a.y + a.z * a.z + a.w * a.w
                 + b.x * b.x + b.y * b.y + b.z * b.z + b.w * b.w;
        #pragma unroll
        for (int o = 16; o; o >>= 1) ss += __shfl_xor_sync(0xffffffffu, ss, o);
        __shared__ float red[8];
        if ((tid & 31) == 0) red[tid >> 5] = ss;
        __syncthreads();
        float tot = red[0] + red[1] + red[2] + red[3] + red[4] + red[5] + red[6] + red[7];
        float inv = rsqrtf(tot * (1.0f / (float)DIMM) + 1.1920929e-7f);

        const float4* wr = (const float4*)w;
        float4 wa = wr[tid];
        float4 wb = wr[tid + 256];
        uint2 o0, o1;
        o0.x = f2h2(a.x * inv * wa.x, a.y * inv * wa.y);
        o0.y = f2h2(a.z * inv * wa.z, a.w * inv * wa.w);
        o1.x = f2h2(b.x * inv * wb.x, b.y * inv * wb.y);
        o1.y = f2h2(b.z * inv * wb.z, b.w * inv * wb.w);
        *(uint2*)&g_xn[(size_t)row * DIMM + tid * 4]        = o0;
        *(uint2*)&g_xn[(size_t)row * DIMM + 1024 + tid * 4] = o1;
    }
}

// ---------------- fp16 GEMM v1: block 128x256, warp 64x64, KSTEP 64, 4-stage (out-proj, fp32 out) ----------------
#define GS 4
#define A_LD 72
#define B_LD 264
#define ASZ (128 * A_LD)
#define BSZ (64 * B_LD)
#define G_SMEM_BYTES (GS * (ASZ + BSZ) * 2)

__global__ void __launch_bounds__(256, 1) gemm_hp(const __half* __restrict__ A,
                                                  const __half* __restrict__ B,
                                                  float* __restrict__ C,
                                                  int M, int N, int K) {
    extern __shared__ __half hsm[];
    __half* As = hsm;
    __half* Bs = hsm + GS * ASZ;

    int tid = threadIdx.x;
    int n0 = blockIdx.x * 256;
    int m0 = blockIdx.y * 128;
    int w = tid >> 5;
    int wm = w >> 2;
    int wn = w & 3;

    wmma::fragment<wmma::accumulator, 16, 16, 16, float> acc[4][4];
    #pragma unroll
    for (int i = 0; i < 4; i++)
        #pragma unroll
        for (int j = 0; j < 4; j++) wmma::fill_fragment(acc[i][j], 0.0f);

    #define LOAD_STAGE(st, kk)                                                          \
        {                                                                               \
            __half* as_ = As + (st) * ASZ;                                              \
            __half* bs_ = Bs + (st) * BSZ;                                              \
            _Pragma("unroll")                                                           \
            for (int i = 0; i < 4; i++) {                                               \
                int c = tid + 256 * i;                                                  \
                int r = c >> 3, c8 = (c & 7) * 8;                                       \
                cpa16(&as_[r * A_LD + c8], &A[(size_t)(m0 + r) * K + (kk) + c8]);       \
            }                                                                           \
            _Pragma("unroll")                                                           \
            for (int i = 0; i < 8; i++) {                                               \
                int c = tid + 256 * i;                                                  \
                int r = c >> 5, c8 = (c & 31) * 8;                                      \
                cpa16(&bs_[r * B_LD + c8], &B[(size_t)((kk) + r) * N + n0 + c8]);       \
            }                                                                           \
            asm volatile("cp.async.commit_group;\n");                                   \
        }

    LOAD_STAGE(0, 0);
    LOAD_STAGE(1, 64);
    LOAD_STAGE(2, 128);

    int nk = K >> 6;
    for (int kt = 0; kt < nk; kt++) {
        int rem = nk - 1 - kt;
        if (rem >= 2)      asm volatile("cp.async.wait_group 2;\n");
        else if (rem == 1) asm volatile("cp.async.wait_group 1;\n");
        else               asm volatile("cp.async.wait_group 0;\n");
        __syncthreads();

        if (kt + 3 < nk) {
            LOAD_STAGE((kt + 3) & 3, (kt + 3) << 6);
        }

        const __half* as = As + (kt & 3) * ASZ;
        const __half* bs = Bs + (kt & 3) * BSZ;

        #pragma unroll
        for (int kf = 0; kf < 4; kf++) {
            wmma::fragment<wmma::matrix_a, 16, 16, 16, __half, wmma::row_major> af[4];
            wmma::fragment<wmma::matrix_b, 16, 16, 16, __half, wmma::row_major> bf[4];
            #pragma unroll
            for (int i = 0; i < 4; i++)
                wmma::load_matrix_sync(af[i], &as[(wm * 64 + i * 16) * A_LD + kf * 16], A_LD);
            #pragma unroll
            for (int j = 0; j < 4; j++)
                wmma::load_matrix_sync(bf[j], &bs[(kf * 16) * B_LD + wn * 64 + j * 16], B_LD);
            #pragma unroll
            for (int i = 0; i < 4; i++)
                #pragma unroll
                for (int j = 0; j < 4; j++)
                    wmma::mma_sync(acc[i][j], af[i], bf[j], acc[i][j]);
        }
    }

    #pragma unroll
    for (int i = 0; i < 4; i++)
        #pragma unroll
        for (int j = 0; j < 4; j++)
            wmma::store_matrix_sync(&C[(size_t)(m0 + wm * 64 + i * 16) * N + n0 + wn * 64 + j * 16],
                                    acc[i][j], N, wmma::mem_row_major);
    #undef LOAD_STAGE
}

// ---------------- fp16 GEMM v2: block 128x192, warp 64x48, KSTEP 64, 4-stage (QKV; half output) ----------------
#define A_LD2 72
#define B_LD2 200
#define ASZ2 (128 * A_LD2)
#define BSZ2 (64 * B_LD2)
#define G2_SMEM_BYTES (GS * (ASZ2 + BSZ2) * 2)

__global__ void __launch_bounds__(256, 1) gemm_hp192(const __half* __restrict__ A,
                                                     const __half* __restrict__ B,
                                                     __half* __restrict__ C,
                                                     int M, int N, int K) {
    extern __shared__ __half hsm[];
    __half* As = hsm;
    __half* Bs = hsm + GS * ASZ2;

    int tid = threadIdx.x;
    int lane = tid & 31;
    int n0 = blockIdx.x * 192;
    int m0 = blockIdx.y * 128;
    int w = tid >> 5;
    int wm = w >> 2;
    int wn = w & 3;

    wmma::fragment<wmma::accumulator, 16, 16, 16, float> acc[4][3];
    #pragma unroll
    for (int i = 0; i < 4; i++)
        #pragma unroll
        for (int j = 0; j < 3; j++) wmma::fill_fragment(acc[i][j], 0.0f);

    #define LOAD_STAGE2(st, kk)                                                         \
        {                                                                               \
            __half* as_ = As + (st) * ASZ2;                                             \
            __half* bs_ = Bs + (st) * BSZ2;                                             \
            _Pragma("unroll")                                                           \
            for (int i = 0; i < 4; i++) {                                               \
                int c = tid + 256 * i;                                                  \
                int r = c >> 3, c8 = (c & 7) * 8;                                       \
                cpa16(&as_[r * A_LD2 + c8], &A[(size_t)(m0 + r) * K + (kk) + c8]);      \
            }                                                                           \
            _Pragma("unroll")                                                           \
            for (int i = 0; i < 6; i++) {                                               \
                int c = tid + 256 * i;                                                  \
                int r = c / 24, cc = (c % 24) * 8;                                      \
                cpa16(&bs_[r * B_LD2 + cc], &B[(size_t)((kk) + r) * N + n0 + cc]);      \
            }                                                                           \
            asm volatile("cp.async.commit_group;\n");                                   \
        }

    LOAD_STAGE2(0, 0);
    LOAD_STAGE2(1, 64);
    LOAD_STAGE2(2, 128);

    int nk = K >> 6;
    for (int kt = 0; kt < nk; kt++) {
        int rem = nk - 1 - kt;
        if (rem >= 2)      asm volatile("cp.async.wait_group 2;\n");
        else if (rem == 1) asm volatile("cp.async.wait_group 1;\n");
        else               asm volatile("cp.async.wait_group 0;\n");
        __syncthreads();

        if (kt + 3 < nk) {
            LOAD_STAGE2((kt + 3) & 3, (kt + 3) << 6);
        }

        const __half* as = As + (kt & 3) * ASZ2;
        const __half* bs = Bs + (kt & 3) * BSZ2;

        #pragma unroll
        for (int kf = 0; kf < 4; kf++) {
            wmma::fragment<wmma::matrix_a, 16, 16, 16, __half, wmma::row_major> af[4];
            wmma::fragment<wmma::matrix_b, 16, 16, 16, __half, wmma::row_major> bf[3];
            #pragma unroll
            for (int i = 0; i < 4; i++)
                wmma::load_matrix_sync(af[i], &as[(wm * 64 + i * 16) * A_LD2 + kf * 16], A_LD2);
            #pragma unroll
            for (int j = 0; j < 3; j++)
                wmma::load_matrix_sync(bf[j], &bs[(kf * 16) * B_LD2 + wn * 48 + j * 16], B_LD2);
            #pragma unroll
            for (int i = 0; i < 4; i++)
                #pragma unroll
                for (int j = 0; j < 3; j++)
                    wmma::mma_sync(acc[i][j], af[i], bf[j], acc[i][j]);
        }
    }

    __syncthreads();
    float* stage = (float*)hsm + w * (16 * 52);
    #pragma unroll
    for (int i = 0; i < 4; i++) {
        #pragma unroll
        for (int j = 0; j < 3; j++)
            wmma::store_matrix_sync(stage + j * 16, acc[i][j], 52, wmma::mem_row_major);
        __syncwarp();
        int rbase = m0 + wm * 64 + i * 16;
        #pragma unroll
        for (int e = 0; e < 12; e++) {
            int idx = lane + e * 32;
            int r = idx / 24, c2 = (idx % 24) * 2;
            float x0 = stage[r * 52 + c2];
            float x1 = stage[r * 52 + c2 + 1];
            *(uint32_t*)&C[(size_t)(rbase + r) * N + n0 + wn * 48 + c2] = f2h2(x0, x1);
        }
        __syncwarp();
    }
    #undef LOAD_STAGE2
}

// ---------------- scatter + rotary: q pre-scaled by 1/sqrt(d) ----------------
#define QSCALE 0.08838834764831845f

__global__ void __launch_bounds__(256) scatter_rotary_kernel(const float* __restrict__ cache,
                                                             float* __restrict__ kv_out) {
    int idx = blockIdx.x * 256 + threadIdx.x;
    int d4 = (idx & 15) * 4;
    int j  = (idx >> 4) & 2047;
    int h  = (idx >> 15) & 15;
    int b  = idx >> 19;

    float4 cl = *(const float4*)&g_cos[j * DD + d4];
    float4 ch = *(const float4*)&g_cos[j * DD + d4 + 64];
    float4 sl = *(const float4*)&g_sin[j * DD + d4];
    float4 sh = *(const float4*)&g_sin[j * DD + d4 + 64];

    float4 kl, kh, vl, vh;
    if (j < 1024) {
        const float* ckb = cache + (((size_t)(b * 2 + 0) * HH + h) * 1024 + j) * DD;
        const float* cvb = cache + (((size_t)(b * 2 + 1) * HH + h) * 1024 + j) * DD;
        kl = *(const float4*)(ckb + d4);
        kh = *(const float4*)(ckb + d4 + 64);
        vl = *(const float4*)(cvb + d4);
        vh = *(const float4*)(cvb + d4 + 64);
    } else {
        int rrow = b * NN + (j - 1024);
        const __half* qr = g_qkv_h + (size_t)rrow * NQKV;
        kl = ld_half4(qr + 2048 + h * DD + d4);
        kh = ld_half4(qr + 2048 + h * DD + d4 + 64);
        vl = ld_half4(qr + 4096 + h * DD + d4);
        vh = ld_half4(qr + 4096 + h * DD + d4 + 64);
        float4 ql = ld_half4(qr + h * DD + d4);
        float4 qh = ld_half4(qr + h * DD + d4 + 64);
        size_t qidx = (((size_t)(b * HH + h) * NN + (j - 1024)) * DD) + d4;
        uint2 qlo, qhi;
        qlo.x = f2h2((ql.x * cl.x - qh.x * sl.x) * QSCALE, (ql.y * cl.y - qh.y * sl.y) * QSCALE);
        qlo.y = f2h2((ql.z * cl.z - qh.z * sl.z) * QSCALE, (ql.w * cl.w - qh.w * sl.w) * QSCALE);
        qhi.x = f2h2((qh.x * ch.x + ql.x * sh.x) * QSCALE, (qh.y * ch.y + ql.y * sh.y) * QSCALE);
        qhi.y = f2h2((qh.z * ch.z + ql.z * sh.z) * QSCALE, (qh.w * ch.w + ql.w * sh.w) * QSCALE);
        *(uint2*)&g_qrot[qidx]      = qlo;
        *(uint2*)&g_qrot[qidx + 64] = qhi;
    }

    size_t kvidx = ((size_t)(b * HH + h) * JJ + j) * DD + d4;
    uint2 klo, khi, vlo, vhi;
    klo.x = f2h2(kl.x * cl.x - kh.x * sl.x, kl.y * cl.y - kh.y * sl.y);
    klo.y = f2h2(kl.z * cl.z - kh.z * sl.z, kl.w * cl.w - kh.w * sl.w);
    khi.x = f2h2(kh.x * ch.x + kl.x * sh.x, kh.y * ch.y + kl.y * sh.y);
    khi.y = f2h2(kh.z * ch.z + kl.z * sh.z, kh.w * ch.w + kl.w * sh.w);
    vlo.x = f2h2(vl.x, vl.y);  vlo.y = f2h2(vl.z, vl.w);
    vhi.x = f2h2(vh.x, vh.y);  vhi.y = f2h2(vh.z, vh.w);
    *(uint2*)&g_krot[kvidx]       = klo;
    *(uint2*)&g_krot[kvidx + 64]  = khi;
    *(uint2*)&g_vfull[kvidx]      = vlo;
    *(uint2*)&g_vfull[kvidx + 64] = vhi;

    float* ko = &kv_out[(((size_t)(b * 2 + 0) * HH + h) * JJ + j) * DD + d4];
    float* vo = &kv_out[(((size_t)(b * 2 + 1) * HH + h) * JJ + j) * DD + d4];
    *(float4*)(ko)      = kl;
    *(float4*)(ko + 64) = kh;
    *(float4*)(vo)      = vl;
    *(float4*)(vo + 64) = vh;
}

// ---------------- flash attention: 128-key tiles, ldmatrix, Q reloaded from smem ----------------
#define KLD 136
#define TILE_H (128 * KLD)
#define AT_SMEM_BYTES (5 * TILE_H * 2 + 2 * 128 * 4)

__global__ void __launch_bounds__(256, 1) attn_kernel(const int* __restrict__ mask) {
    extern __shared__ char asmem[];
    __half* Qs = (__half*)asmem;
    __half* Kb[2] = { Qs + 1 * TILE_H, Qs + 3 * TILE_H };
    __half* Vb[2] = { Qs + 2 * TILE_H, Qs + 4 * TILE_H };
    int* Ms = (int*)(Qs + 5 * TILE_H);

    int tid = threadIdx.x;
    int w = tid >> 5;
    int lane = tid & 31;
    int g = lane >> 2;
    int t2 = (lane & 3) * 2;

    int bid = blockIdx.x;
    int b  = bid & 3;
    int h  = (bid >> 2) & 15;
    int qb = 7 - (bid >> 6);
    int m0 = qb * 128;

    const __half* qp = g_qrot + ((size_t)(b * HH + h) * NN + m0) * DD;
    const __half* kp = g_krot + (size_t)(b * HH + h) * JJ * DD;
    const __half* vp = g_vfull + (size_t)(b * HH + h) * JJ * DD;
    const int* mrow = mask + (size_t)b * JJ;

    int nt = qb + 9;

    #pragma unroll
    for (int i = tid; i < 128 * 16; i += 256) {
        int r = i >> 4, c8 = (i & 15) * 8;
        *(float4*)&Qs[r * KLD + c8] = *(const float4*)&qp[(size_t)r * DD + c8];
    }
    if (tid < 128) Ms[tid] = mrow[tid];
    #pragma unroll
    for (int i = tid; i < 128 * 16; i += 256) {
        int r = i >> 4, c8 = (i & 15) * 8;
        cpa16(&Kb[0][r * KLD + c8], &kp[(size_t)r * DD + c8]);
    }
    asm volatile("cp.async.commit_group;\n");
    #pragma unroll
    for (int i = tid; i < 128 * 16; i += 256) {
        int r = i >> 4, c8 = (i & 15) * 8;
        cpa16(&Vb[0][r * KLD + c8], &vp[(size_t)r * DD + c8]);
    }
    asm volatile("cp.async.commit_group;\n");
    __syncthreads();

    float oc[16][4];
    #pragma unroll
    for (int n = 0; n < 16; n++)
        #pragma unroll
        for (int i = 0; i < 4; i++) oc[n][i] = 0.0f;

    float m0r = -1e30f, m1r = -1e30f;
    float l0 = 0.0f, l1 = 0.0f;
    int row0 = m0 + w * 16 + g;
    int rowlim0 = row0 + 1024;
    int rowlim1 = rowlim0 + 8;

    // ldmatrix per-lane offsets (bytes)
    uint32_t qoff = ((w * 16 + (lane & 7) + ((lane >> 3) & 1) * 8) * KLD + (lane >> 4) * 8) * 2;
    uint32_t koff = ((lane & 7) * KLD + (lane >> 3) * 8) * 2;
    uint32_t voff = ((((lane >> 3) & 1) * 8 + (lane & 7)) * KLD + (lane >> 4) * 8) * 2;
    uint32_t qbase = smem_u32(Qs) + qoff;

    for (int kt = 0; kt < nt; kt++) {
        asm volatile("cp.async.wait_group 0;\n");
        __syncthreads();

        if (tid < 128 && kt + 1 < nt) Ms[((kt + 1) & 1) * 128 + tid] = mrow[(kt + 1) * 128 + tid];

        if (kt + 1 < nt) {
            int bn = (kt + 1) & 1;
            #pragma unroll
            for (int i = tid; i < 128 * 16; i += 256) {
                int r = i >> 4, c8 = (i & 15) * 8;
                cpa16(&Kb[bn][r * KLD + c8], &kp[(size_t)((kt + 1) * 128 + r) * DD + c8]);
            }
            asm volatile("cp.async.commit_group;\n");
            #pragma unroll
            for (int i = tid; i < 128 * 16; i += 256) {
                int r = i >> 4, c8 = (i & 15) * 8;
                cpa16(&Vb[bn][r * KLD + c8], &vp[(size_t)((kt + 1) * 128 + r) * DD + c8]);
            }
            asm volatile("cp.async.commit_group;\n");
        }

        const __half* Kt = Kb[kt & 1];
        const __half* Vt = Vb[kt & 1];
        const int* Mt = Ms + (kt & 1) * 128;

        // S = Q K^T (Q pre-scaled); Q fragments reloaded from smem per k-slab
        float sc[16][4];
        #pragma unroll
        for (int n = 0; n < 16; n++)
            #pragma unroll
            for (int i = 0; i < 4; i++) sc[n][i] = 0.0f;

        uint32_t ktu = smem_u32(Kt) + koff;
        #pragma unroll
        for (int ksp = 0; ksp < 4; ksp++) {
            uint32_t qa0[4], qa1[4];
            ldsm4(qa0, qbase + (uint32_t)(ksp * 32) * 2);
            ldsm4(qa1, qbase + (uint32_t)(ksp * 32 + 16) * 2);
            #pragma unroll
            for (int nb = 0; nb < 16; nb++) {
                uint32_t br[4];
                ldsm4(br, ktu + (uint32_t)(nb * 8 * KLD + ksp * 32) * 2);
                mma16816(sc[nb], qa0, br[0], br[1]);
                mma16816(sc[nb], qa1, br[2], br[3]);
            }
        }

        // mask + row max
        bool lastt = (kt == nt - 1);
        float mx0 = -1e30f, mx1 = -1e30f;
        #pragma unroll
        for (int nb = 0; nb < 16; nb++) {
            int col = kt * 128 + nb * 8 + t2;
            int2 mv = *(const int2*)&Mt[nb * 8 + t2];
            float v0 = sc[nb][0];
            float v1 = sc[nb][1];
            float v2 = sc[nb][2];
            float v3 = sc[nb][3];
            if (mv.x == 0) { v0 = -1e30f; v2 = -1e30f; }
            if (mv.y == 0) { v1 = -1e30f; v3 = -1e30f; }
            if (lastt) {
                if (col     > rowlim0) v0 = -1e30f;
                if (col + 1 > rowlim0) v1 = -1e30f;
                if (col     > rowlim1) v2 = -1e30f;
                if (col + 1 > rowlim1) v3 = -1e30f;
            }
            sc[nb][0] = v0; sc[nb][1] = v1; sc[nb][2] = v2; sc[nb][3] = v3;
            mx0 = fmaxf(mx0, fmaxf(v0, v1));
            mx1 = fmaxf(mx1, fmaxf(v2, v3));
        }
        mx0 = fmaxf(mx0, __shfl_xor_sync(0xffffffffu, mx0, 1));
        mx0 = fmaxf(mx0, __shfl_xor_sync(0xffffffffu, mx0, 2));
        mx1 = fmaxf(mx1, __shfl_xor_sync(0xffffffffu, mx1, 1));
        mx1 = fmaxf(mx1, __shfl_xor_sync(0xffffffffu, mx1, 2));

        float mn0 = fmaxf(m0r, mx0), mn1 = fmaxf(m1r, mx1);
        float al0 = __expf(m0r - mn0), al1 = __expf(m1r - mn1);
        m0r = mn0; m1r = mn1;

        // exp + immediate pack to half (sc dies here)
        uint32_t ph0[16], ph1[16];
        float s0 = 0.0f, s1 = 0.0f;
        #pragma unroll
        for (int nb = 0; nb < 16; nb++) {
            float p0 = __expf(sc[nb][0] - mn0);
            float p1 = __expf(sc[nb][1] - mn0);
            float p2 = __expf(sc[nb][2] - mn1);
            float p3 = __expf(sc[nb][3] - mn1);
            s0 += p0 + p1; s1 += p2 + p3;
            ph0[nb] = f2h2(p0, p1);
            ph1[nb] = f2h2(p2, p3);
        }
        l0 = l0 * al0 + s0;
        l1 = l1 * al1 + s1;
        #pragma unroll
        for (int n = 0; n < 16; n++) {
            oc[n][0] *= al0; oc[n][1] *= al0;
            oc[n][2] *= al1; oc[n][3] *= al1;
        }

        // PV
        uint32_t vtu = smem_u32(Vt) + voff;
        #pragma unroll
        for (int kk = 0; kk < 8; kk++) {
            uint32_t pa[4];
            pa[0] = ph0[2 * kk];
            pa[1] = ph1[2 * kk];
            pa[2] = ph0[2 * kk + 1];
            pa[3] = ph1[2 * kk + 1];
            #pragma unroll
            for (int ndp = 0; ndp < 8; ndp++) {
                uint32_t br[4];
                ldsm4t(br, vtu + (uint32_t)(kk * 16 * KLD + ndp * 16) * 2);
                mma16816(oc[2 * ndp],     pa, br[0], br[1]);
                mma16816(oc[2 * ndp + 1], pa, br[2], br[3]);
            }
        }
    }

    l0 += __shfl_xor_sync(0xffffffffu, l0, 1);
    l0 += __shfl_xor_sync(0xffffffffu, l0, 2);
    l1 += __shfl_xor_sync(0xffffffffu, l1, 1);
    l1 += __shfl_xor_sync(0xffffffffu, l1, 2);
    float inv0 = 1.0f / l0, inv1 = 1.0f / l1;

    __half* out0 = g_attnout + (size_t)(b * NN + row0) * DIMM + h * DD;
    __half* out1 = out0 + (size_t)8 * DIMM;
    #pragma unroll
    for (int nd = 0; nd < 16; nd++) {
        *(uint32_t*)&out0[nd * 8 + t2] = f2h2(oc[nd][0] * inv0, oc[nd][1] * inv0);
        *(uint32_t*)&out1[nd * 8 + t2] = f2h2(oc[nd][2] * inv1, oc[nd][3] * inv1);
    }
}

// ---------------- launch ----------------
extern "C" void kernel_launch(void* const* d_in, const int* in_sizes, int n_in,
                              void* d_out, int out_size) {
    const float* x       = (const float*)d_in[0];
    const float* cache   = (const float*)d_in[1];
    const float* rotary  = (const float*)d_in[2];
    const int*   mask    = (const int*)d_in[3];
    const float* norm_w  = (const float*)d_in[4];
    const float* w_qkv   = (const float*)d_in[5];
    const float* w_out   = (const float*)d_in[6];

    float* out    = (float*)d_out;
    float* kv_out = out + (size_t)ROWS * DIMM;

    __half *xn_ptr, *wqkv_ptr, *wout_ptr, *ao_ptr, *qkvh_ptr;
    cudaGetSymbolAddress((void**)&xn_ptr, g_xn);
    cudaGetSymbolAddress((void**)&qkvh_ptr, g_qkv_h);
    cudaGetSymbolAddress((void**)&ao_ptr, g_attnout);
    cudaGetSymbolAddress((void**)&wqkv_ptr, g_wqkv_h);
    cudaGetSymbolAddress((void**)&wout_ptr, g_wout_h);

    cudaFuncSetAttribute(attn_kernel, cudaFuncAttributeMaxDynamicSharedMemorySize, AT_SMEM_BYTES);
    cudaFuncSetAttribute(gemm_hp, cudaFuncAttributeMaxDynamicSharedMemorySize, G_SMEM_BYTES);
    cudaFuncSetAttribute(gemm_hp192, cudaFuncAttributeMaxDynamicSharedMemorySize, G2_SMEM_BYTES);

    prep_kernel<<<PREP_BLKS, 256>>>(rotary, w_qkv, w_out, x, norm_w);

    gemm_hp192<<<dim3(NQKV / 192, ROWS / 128), 256, G2_SMEM_BYTES>>>(xn_ptr, wqkv_ptr, qkvh_ptr,
                                                                     ROWS, NQKV, DIMM);

    scatter_rotary_kernel<<<(BB * HH * JJ * 16) / 256, 256>>>(cache, kv_out);

    attn_kernel<<<BB * HH * (NN / 128), 256, AT_SMEM_BYTES>>>(mask);

    gemm_hp<<<dim3(DIMM / 256, ROWS / 128), 256, G_SMEM_BYTES>>>(ao_ptr, wout_ptr, out,
                                                                 ROWS, DIMM, DIMM);
}